// round 5
// baseline (speedup 1.0000x reference)
#include <cuda_runtime.h>
#include <math.h>

#define NNODES 100000
#define NEDGES 1600000
#define FIN 128
#define FOUT 64

// ---------------- scratch (device globals; 16B-aligned) ----------------
__device__ __align__(16) int   g_ecnt[NNODES];
__device__ __align__(16) int   g_rowptr[NNODES + 1];
__device__ __align__(16) int   g_cursor[NNODES];
__device__ __align__(16) int   g_col[NEDGES];
__device__ __align__(16) float g_dinv[NNODES];
__device__ __align__(16) float g_h [NNODES * FOUT];   // h' = (x@W)*dinv
__device__ __align__(16) float g_t1[NNODES * FOUT];   // x_temp (residual)
__device__ __align__(16) float g_t2[NNODES * FOUT];   // layer-2 activation
__device__ int g_is64;                                 // edge_index dtype flag

// ---------------- dtype detector ----------------
// int64 indices < 100000 have zero high words; int32 data reinterpreted as
// int64 puts a second (almost surely nonzero) index in the high word.
__global__ void k_detect(const void* __restrict__ ei) {
    const unsigned long long* p = (const unsigned long long*)ei;
    __shared__ unsigned int s;
    if (threadIdx.x == 0) s = 0u;
    __syncthreads();
    unsigned int any = 0u;
    for (int i = threadIdx.x; i < 4096; i += 256)
        any |= (unsigned int)(p[i] >> 32);
    atomicOr(&s, any);
    __syncthreads();
    if (threadIdx.x == 0) g_is64 = (s == 0u) ? 1 : 0;
}

__device__ __forceinline__ int load_idx(const int* __restrict__ ei32, long long pos) {
    if (g_is64) return (int)((const long long*)ei32)[pos];
    return ei32[pos];
}

// ---------------- CSR build ----------------
__global__ void k_zero() {
    int i = blockIdx.x * blockDim.x + threadIdx.x;
    if (i < NNODES) g_ecnt[i] = 0;
}

__global__ void k_count(const int* __restrict__ ei32) {
    int e = blockIdx.x * blockDim.x + threadIdx.x;
    if (e < NEDGES) {
        int d = load_idx(ei32, (long long)NEDGES + e);
        if ((unsigned)d < (unsigned)NNODES) atomicAdd(&g_ecnt[d], 1);
    }
}

// single-block scan: ecnt -> rowptr/cursor, and dinv = rsqrt(deg+1)
__global__ void k_scan() {
    __shared__ int ssum[1024];
    const int t = threadIdx.x;
    const int CH = (NNODES + 1023) / 1024;   // 98
    int beg = t * CH;
    int end = beg + CH;
    if (end > NNODES) end = NNODES;
    if (beg > NNODES) beg = NNODES;
    int s = 0;
    for (int i = beg; i < end; i++) s += g_ecnt[i];
    ssum[t] = s;
    __syncthreads();
    for (int off = 1; off < 1024; off <<= 1) {
        int v = ssum[t];
        int add = (t >= off) ? ssum[t - off] : 0;
        __syncthreads();
        ssum[t] = v + add;
        __syncthreads();
    }
    int run = (t == 0) ? 0 : ssum[t - 1];
    for (int i = beg; i < end; i++) {
        int c = g_ecnt[i];
        g_rowptr[i] = run;
        g_cursor[i] = run;
        g_dinv[i]   = rsqrtf((float)(c + 1));   // +1 self-loop; always > 0
        run += c;
    }
    if (t == 0) g_rowptr[NNODES] = ssum[1023];
}

__global__ void k_fill(const int* __restrict__ ei32) {
    int e = blockIdx.x * blockDim.x + threadIdx.x;
    if (e < NEDGES) {
        int d = load_idx(ei32, (long long)NEDGES + e);
        int s = load_idx(ei32, e);
        if ((unsigned)d < (unsigned)NNODES && (unsigned)s < (unsigned)NNODES) {
            int p = atomicAdd(&g_cursor[d], 1);
            g_col[p] = s;
        }
    }
}

// ---------------- GEMM: g_h[n,:] = (X[n,:] @ W) * dinv[n] ----------------
// 256 threads = 8 warps, 4 nodes/warp -> 32 nodes/block. K chunked by 64.
// SEL: 0 = external X, 1 = g_t1, 2 = g_t2 (compile-time only).
template <int K, int SEL>
__global__ __launch_bounds__(256) void k_gemm(const float* __restrict__ Xext,
                                              const float* __restrict__ W) {
    __shared__ __align__(16) float wsm[64 * FOUT];
    __shared__ __align__(16) float xsm[32 * 64];

    const float* X;
    if constexpr (SEL == 0)      X = Xext;
    else if constexpr (SEL == 1) X = g_t1;
    else                         X = g_t2;

    const int tid  = threadIdx.x;
    const int warp = tid >> 5;
    const int lane = tid & 31;
    const int base = blockIdx.x * 32;               // NNODES % 32 == 0

    float2 a0 = {0.f, 0.f}, a1 = {0.f, 0.f}, a2 = {0.f, 0.f}, a3 = {0.f, 0.f};

#pragma unroll
    for (int kc = 0; kc < K; kc += 64) {
        for (int i = tid; i < 64 * FOUT; i += 256)
            wsm[i] = W[kc * FOUT + i];
        for (int i = tid; i < 32 * 64; i += 256) {
            int r = i >> 6, c = i & 63;
            xsm[i] = X[(size_t)(base + r) * K + kc + c];
        }
        __syncthreads();

        const float* x0 = &xsm[(warp * 4 + 0) * 64];
        const float* x1 = &xsm[(warp * 4 + 1) * 64];
        const float* x2 = &xsm[(warp * 4 + 2) * 64];
        const float* x3 = &xsm[(warp * 4 + 3) * 64];

#pragma unroll 8
        for (int k = 0; k < 64; k++) {
            float2 w = *(const float2*)&wsm[k * FOUT + 2 * lane];
            float v0 = x0[k], v1 = x1[k], v2 = x2[k], v3 = x3[k];
            a0.x = fmaf(v0, w.x, a0.x); a0.y = fmaf(v0, w.y, a0.y);
            a1.x = fmaf(v1, w.x, a1.x); a1.y = fmaf(v1, w.y, a1.y);
            a2.x = fmaf(v2, w.x, a2.x); a2.y = fmaf(v2, w.y, a2.y);
            a3.x = fmaf(v3, w.x, a3.x); a3.y = fmaf(v3, w.y, a3.y);
        }
        __syncthreads();
    }

    const int n0 = base + warp * 4;
    float s0 = g_dinv[n0 + 0], s1 = g_dinv[n0 + 1];
    float s2 = g_dinv[n0 + 2], s3 = g_dinv[n0 + 3];
    const int off = 2 * lane;
    *(float2*)&g_h[(size_t)(n0 + 0) * FOUT + off] = make_float2(a0.x * s0, a0.y * s0);
    *(float2*)&g_h[(size_t)(n0 + 1) * FOUT + off] = make_float2(a1.x * s1, a1.y * s1);
    *(float2*)&g_h[(size_t)(n0 + 2) * FOUT + off] = make_float2(a2.x * s2, a2.y * s2);
    *(float2*)&g_h[(size_t)(n0 + 3) * FOUT + off] = make_float2(a3.x * s3, a3.y * s3);
}

// ---------------- aggregation ----------------
// out[i] = f(dinv[i]*(g_h[i] + sum_{src->i} g_h[src]) + bias)
// MODE 0: identity -> g_t1 | MODE 1: relu -> g_t2 | MODE 2: relu + g_t1 -> ext out
template <int MODE>
__global__ __launch_bounds__(256) void k_agg(const float* __restrict__ bias,
                                             float* __restrict__ outext) {
    const int warp = threadIdx.x >> 5;
    const int lane = threadIdx.x & 31;
    const int node = blockIdx.x * 8 + warp;
    if (node >= NNODES) return;

    float* out;
    if constexpr (MODE == 0)      out = g_t1;
    else if constexpr (MODE == 1) out = g_t2;
    else                          out = outext;

    const int beg = g_rowptr[node];
    const int end = g_rowptr[node + 1];
    const int off = 2 * lane;

    float2 acc = *(const float2*)&g_h[(size_t)node * FOUT + off];   // self-loop

    int p = beg;
    for (; p + 4 <= end; p += 4) {
        int s0 = g_col[p], s1 = g_col[p + 1], s2 = g_col[p + 2], s3 = g_col[p + 3];
        float2 b0 = *(const float2*)&g_h[(size_t)s0 * FOUT + off];
        float2 b1 = *(const float2*)&g_h[(size_t)s1 * FOUT + off];
        float2 b2 = *(const float2*)&g_h[(size_t)s2 * FOUT + off];
        float2 b3 = *(const float2*)&g_h[(size_t)s3 * FOUT + off];
        acc.x += (b0.x + b1.x) + (b2.x + b3.x);
        acc.y += (b0.y + b1.y) + (b2.y + b3.y);
    }
    for (; p < end; p++) {
        int s = g_col[p];
        float2 b = *(const float2*)&g_h[(size_t)s * FOUT + off];
        acc.x += b.x; acc.y += b.y;
    }

    const float di = g_dinv[node];
    float2 bb = *(const float2*)&bias[off];
    float rx = fmaf(di, acc.x, bb.x);
    float ry = fmaf(di, acc.y, bb.y);
    if (MODE >= 1) { rx = fmaxf(rx, 0.f); ry = fmaxf(ry, 0.f); }
    if (MODE == 2) {
        float2 r = *(const float2*)&g_t1[(size_t)node * FOUT + off];
        rx += r.x; ry += r.y;
    }
    *(float2*)&out[(size_t)node * FOUT + off] = make_float2(rx, ry);
}

// ---------------- launch ----------------
extern "C" void kernel_launch(void* const* d_in, const int* in_sizes, int n_in,
                              void* d_out, int out_size) {
    const float* x  = (const float*)d_in[0];
    const int*   ei = (const int*)d_in[1];     // int32 or int64; detected on device
    const float* W0 = (const float*)d_in[2];
    const float* b0 = (const float*)d_in[3];
    const float* Ws = (const float*)d_in[4];
    const float* bs = (const float*)d_in[5];
    float*       out = (float*)d_out;

    const int NB_N = (NNODES + 255) / 256;
    const int NB_E = (NEDGES + 255) / 256;
    const int NB_G = NNODES / 32;            // 3125 (exact)
    const int NB_A = (NNODES + 7) / 8;       // 12500

    // CSR build (per call; deterministic)
    k_detect<<<1, 256>>>(ei);
    k_zero  <<<NB_N, 256>>>();
    k_count <<<NB_E, 256>>>(ei);
    k_scan  <<<1, 1024>>>();
    k_fill  <<<NB_E, 256>>>(ei);

    // layer 1: t1 = conv(x, W0, b0)
    k_gemm<FIN, 0> <<<NB_G, 256>>>(x, W0);
    k_agg<0>       <<<NB_A, 256>>>(b0, nullptr);

    // layer 2: t2 = relu(conv(t1, Ws[0], bs[0]))
    k_gemm<FOUT, 1><<<NB_G, 256>>>(nullptr, Ws);
    k_agg<1>       <<<NB_A, 256>>>(bs, nullptr);

    // layer 3: out = relu(conv(t2, Ws[1], bs[1])) + t1
    k_gemm<FOUT, 2><<<NB_G, 256>>>(nullptr, Ws + FOUT * FOUT);
    k_agg<2>       <<<NB_A, 256>>>(bs + FOUT, out);
}

// round 6
// speedup vs baseline: 1.6823x; 1.6823x over previous
#include <cuda_runtime.h>
#include <math.h>

#define NNODES 100000
#define NEDGES 1600000
#define FIN 128
#define FOUT 64
#define SCAN_NB ((NNODES + 1023) / 1024)   // 98

// ---------------- scratch (device globals; 16B-aligned) ----------------
__device__ __align__(16) int   g_ecnt[NNODES];
__device__ __align__(16) int   g_incl[NNODES];        // block-local inclusive scan
__device__ __align__(16) int   g_bsum[SCAN_NB];       // block totals -> exclusive offsets
__device__ __align__(16) int   g_rowptr[NNODES + 1];
__device__ __align__(16) int   g_cursor[NNODES];
__device__ __align__(16) int   g_col[NEDGES];
__device__ __align__(16) float g_dinv[NNODES];
__device__ __align__(16) float g_h [NNODES * FOUT];   // h' = (x@W)*dinv
__device__ __align__(16) float g_t1[NNODES * FOUT];   // x_temp (residual)
__device__ __align__(16) float g_t2[NNODES * FOUT];   // layer-2 activation
__device__ int g_is64;                                 // edge_index dtype flag

// ---------------- dtype detector ----------------
__global__ void k_detect(const void* __restrict__ ei) {
    const unsigned long long* p = (const unsigned long long*)ei;
    __shared__ unsigned int s;
    if (threadIdx.x == 0) s = 0u;
    __syncthreads();
    unsigned int any = 0u;
    for (int i = threadIdx.x; i < 4096; i += 256)
        any |= (unsigned int)(p[i] >> 32);
    atomicOr(&s, any);
    __syncthreads();
    if (threadIdx.x == 0) g_is64 = (s == 0u) ? 1 : 0;
}

__device__ __forceinline__ int load_idx(const int* __restrict__ ei32, long long pos) {
    if (g_is64) return (int)((const long long*)ei32)[pos];
    return ei32[pos];
}

// ---------------- CSR build ----------------
__global__ void k_zero() {
    int i = blockIdx.x * blockDim.x + threadIdx.x;
    if (i < NNODES) g_ecnt[i] = 0;
}

__global__ void k_count(const int* __restrict__ ei32) {
    int e = blockIdx.x * blockDim.x + threadIdx.x;
    if (e < NEDGES) {
        int d = load_idx(ei32, (long long)NEDGES + e);
        if ((unsigned)d < (unsigned)NNODES) atomicAdd(&g_ecnt[d], 1);
    }
}

// phase 1: per-block inclusive scan of ecnt (warp shuffles), block totals out
__global__ __launch_bounds__(1024) void k_scan1() {
    __shared__ int wsum[32];
    const int i    = blockIdx.x * 1024 + threadIdx.x;
    const int lane = threadIdx.x & 31;
    const int warp = threadIdx.x >> 5;
    int v = (i < NNODES) ? g_ecnt[i] : 0;
    int x = v;
#pragma unroll
    for (int o = 1; o < 32; o <<= 1) {
        int y = __shfl_up_sync(0xffffffffu, x, o);
        if (lane >= o) x += y;
    }
    if (lane == 31) wsum[warp] = x;
    __syncthreads();
    if (warp == 0) {
        int s = wsum[lane];
#pragma unroll
        for (int o = 1; o < 32; o <<= 1) {
            int y = __shfl_up_sync(0xffffffffu, s, o);
            if (lane >= o) s += y;
        }
        wsum[lane] = s;
    }
    __syncthreads();
    int incl = x + (warp > 0 ? wsum[warp - 1] : 0);
    if (i < NNODES) g_incl[i] = incl;
    if (threadIdx.x == 1023) g_bsum[blockIdx.x] = incl;   // block total
}

// phase 2: exclusive scan of the 98 block totals; total -> rowptr[NNODES]
__global__ void k_scan2() {
    __shared__ int s[128];
    const int t = threadIdx.x;
    s[t] = (t < SCAN_NB) ? g_bsum[t] : 0;
    __syncthreads();
    for (int o = 1; o < 128; o <<= 1) {
        int x = s[t];
        int add = (t >= o) ? s[t - o] : 0;
        __syncthreads();
        s[t] = x + add;
        __syncthreads();
    }
    if (t < SCAN_NB) g_bsum[t] = (t == 0) ? 0 : s[t - 1];
    if (t == 0) g_rowptr[NNODES] = s[SCAN_NB - 1];
}

// phase 3: rowptr/cursor/dinv from offset + inclusive partial
__global__ __launch_bounds__(1024) void k_scan3() {
    const int i = blockIdx.x * 1024 + threadIdx.x;
    if (i < NNODES) {
        int c = g_ecnt[i];
        int start = g_bsum[blockIdx.x] + g_incl[i] - c;
        g_rowptr[i] = start;
        g_cursor[i] = start;
        g_dinv[i]   = rsqrtf((float)(c + 1));   // +1 self-loop; always > 0
    }
}

__global__ void k_fill(const int* __restrict__ ei32) {
    int e = blockIdx.x * blockDim.x + threadIdx.x;
    if (e < NEDGES) {
        int d = load_idx(ei32, (long long)NEDGES + e);
        int s = load_idx(ei32, e);
        if ((unsigned)d < (unsigned)NNODES && (unsigned)s < (unsigned)NNODES) {
            int p = atomicAdd(&g_cursor[d], 1);
            g_col[p] = s;
        }
    }
}

// ---------------- GEMM: g_h[n,:] = (X[n,:] @ W) * dinv[n] ----------------
template <int K, int SEL>
__global__ __launch_bounds__(256) void k_gemm(const float* __restrict__ Xext,
                                              const float* __restrict__ W) {
    __shared__ __align__(16) float wsm[64 * FOUT];
    __shared__ __align__(16) float xsm[32 * 64];

    const float* X;
    if constexpr (SEL == 0)      X = Xext;
    else if constexpr (SEL == 1) X = g_t1;
    else                         X = g_t2;

    const int tid  = threadIdx.x;
    const int warp = tid >> 5;
    const int lane = tid & 31;
    const int base = blockIdx.x * 32;               // NNODES % 32 == 0

    float2 a0 = {0.f, 0.f}, a1 = {0.f, 0.f}, a2 = {0.f, 0.f}, a3 = {0.f, 0.f};

#pragma unroll
    for (int kc = 0; kc < K; kc += 64) {
        for (int i = tid; i < 64 * FOUT; i += 256)
            wsm[i] = W[kc * FOUT + i];
        for (int i = tid; i < 32 * 64; i += 256) {
            int r = i >> 6, c = i & 63;
            xsm[i] = X[(size_t)(base + r) * K + kc + c];
        }
        __syncthreads();

        const float* x0 = &xsm[(warp * 4 + 0) * 64];
        const float* x1 = &xsm[(warp * 4 + 1) * 64];
        const float* x2 = &xsm[(warp * 4 + 2) * 64];
        const float* x3 = &xsm[(warp * 4 + 3) * 64];

#pragma unroll 8
        for (int k = 0; k < 64; k++) {
            float2 w = *(const float2*)&wsm[k * FOUT + 2 * lane];
            float v0 = x0[k], v1 = x1[k], v2 = x2[k], v3 = x3[k];
            a0.x = fmaf(v0, w.x, a0.x); a0.y = fmaf(v0, w.y, a0.y);
            a1.x = fmaf(v1, w.x, a1.x); a1.y = fmaf(v1, w.y, a1.y);
            a2.x = fmaf(v2, w.x, a2.x); a2.y = fmaf(v2, w.y, a2.y);
            a3.x = fmaf(v3, w.x, a3.x); a3.y = fmaf(v3, w.y, a3.y);
        }
        __syncthreads();
    }

    const int n0 = base + warp * 4;
    float s0 = g_dinv[n0 + 0], s1 = g_dinv[n0 + 1];
    float s2 = g_dinv[n0 + 2], s3 = g_dinv[n0 + 3];
    const int off = 2 * lane;
    *(float2*)&g_h[(size_t)(n0 + 0) * FOUT + off] = make_float2(a0.x * s0, a0.y * s0);
    *(float2*)&g_h[(size_t)(n0 + 1) * FOUT + off] = make_float2(a1.x * s1, a1.y * s1);
    *(float2*)&g_h[(size_t)(n0 + 2) * FOUT + off] = make_float2(a2.x * s2, a2.y * s2);
    *(float2*)&g_h[(size_t)(n0 + 3) * FOUT + off] = make_float2(a3.x * s3, a3.y * s3);
}

// ---------------- aggregation ----------------
// MODE 0: identity -> g_t1 | MODE 1: relu -> g_t2 | MODE 2: relu + g_t1 -> ext out
template <int MODE>
__global__ __launch_bounds__(256) void k_agg(const float* __restrict__ bias,
                                             float* __restrict__ outext) {
    const int warp = threadIdx.x >> 5;
    const int lane = threadIdx.x & 31;
    const int node = blockIdx.x * 8 + warp;
    if (node >= NNODES) return;

    float* out;
    if constexpr (MODE == 0)      out = g_t1;
    else if constexpr (MODE == 1) out = g_t2;
    else                          out = outext;

    const int beg = g_rowptr[node];
    const int end = g_rowptr[node + 1];
    const int off = 2 * lane;

    float2 acc = *(const float2*)&g_h[(size_t)node * FOUT + off];   // self-loop

    int p = beg;
    for (; p + 4 <= end; p += 4) {
        int s0 = g_col[p], s1 = g_col[p + 1], s2 = g_col[p + 2], s3 = g_col[p + 3];
        float2 b0 = *(const float2*)&g_h[(size_t)s0 * FOUT + off];
        float2 b1 = *(const float2*)&g_h[(size_t)s1 * FOUT + off];
        float2 b2 = *(const float2*)&g_h[(size_t)s2 * FOUT + off];
        float2 b3 = *(const float2*)&g_h[(size_t)s3 * FOUT + off];
        acc.x += (b0.x + b1.x) + (b2.x + b3.x);
        acc.y += (b0.y + b1.y) + (b2.y + b3.y);
    }
    for (; p < end; p++) {
        int s = g_col[p];
        float2 b = *(const float2*)&g_h[(size_t)s * FOUT + off];
        acc.x += b.x; acc.y += b.y;
    }

    const float di = g_dinv[node];
    float2 bb = *(const float2*)&bias[off];
    float rx = fmaf(di, acc.x, bb.x);
    float ry = fmaf(di, acc.y, bb.y);
    if (MODE >= 1) { rx = fmaxf(rx, 0.f); ry = fmaxf(ry, 0.f); }
    if (MODE == 2) {
        float2 r = *(const float2*)&g_t1[(size_t)node * FOUT + off];
        rx += r.x; ry += r.y;
    }
    *(float2*)&out[(size_t)node * FOUT + off] = make_float2(rx, ry);
}

// ---------------- launch ----------------
extern "C" void kernel_launch(void* const* d_in, const int* in_sizes, int n_in,
                              void* d_out, int out_size) {
    const float* x  = (const float*)d_in[0];
    const int*   ei = (const int*)d_in[1];     // int32 or int64; detected on device
    const float* W0 = (const float*)d_in[2];
    const float* b0 = (const float*)d_in[3];
    const float* Ws = (const float*)d_in[4];
    const float* bs = (const float*)d_in[5];
    float*       out = (float*)d_out;

    const int NB_N = (NNODES + 255) / 256;
    const int NB_E = (NEDGES + 255) / 256;
    const int NB_G = NNODES / 32;            // 3125 (exact)
    const int NB_A = (NNODES + 7) / 8;       // 12500

    // CSR build (per call; deterministic)
    k_detect<<<1, 256>>>(ei);
    k_zero  <<<NB_N, 256>>>();
    k_count <<<NB_E, 256>>>(ei);
    k_scan1 <<<SCAN_NB, 1024>>>();
    k_scan2 <<<1, 128>>>();
    k_scan3 <<<SCAN_NB, 1024>>>();
    k_fill  <<<NB_E, 256>>>(ei);

    // layer 1: t1 = conv(x, W0, b0)
    k_gemm<FIN, 0> <<<NB_G, 256>>>(x, W0);
    k_agg<0>       <<<NB_A, 256>>>(b0, nullptr);

    // layer 2: t2 = relu(conv(t1, Ws[0], bs[0]))
    k_gemm<FOUT, 1><<<NB_G, 256>>>(nullptr, Ws);
    k_agg<1>       <<<NB_A, 256>>>(bs, nullptr);

    // layer 3: out = relu(conv(t2, Ws[1], bs[1])) + t1
    k_gemm<FOUT, 2><<<NB_G, 256>>>(nullptr, Ws + FOUT * FOUT);
    k_agg<2>       <<<NB_A, 256>>>(bs + FOUT, out);
}